// round 4
// baseline (speedup 1.0000x reference)
#include <cuda_runtime.h>
#include <math.h>

// ---------------------------------------------------------------------------
// Problem constants (fixed by the dataset)
// ---------------------------------------------------------------------------
#define NNODES 50000
#define NEDGES 1000000
#define FDIM   256
#define NCDIM  300
#define EDDIM  64

// ---------------------------------------------------------------------------
// Scratch (device globals — no allocation allowed)
// ---------------------------------------------------------------------------
__device__ float g_c[NNODES * NCDIM];   // content projection intermediate [N,300]
__device__ float g_t[NNODES * FDIM];    // temp [N,256]
__device__ float g_h[NNODES * FDIM];    // node features h [N,256]
__device__ float g_g[NNODES * FDIM];    // h_agg / Wo intermediate [N,256]
__device__ int   g_deg[NNODES];
__device__ int   g_off[NNODES + 1];
__device__ int   g_cur[NNODES];
__device__ int   g_csr[NEDGES];

// ---------------------------------------------------------------------------
// Small utility kernels
// ---------------------------------------------------------------------------
__global__ void zero_int_kernel(int* p, int n) {
    int i = blockIdx.x * blockDim.x + threadIdx.x;
    if (i < n) p[i] = 0;
}

__global__ void deg_kernel(const int* __restrict__ dst, int* __restrict__ deg, int e) {
    int i = blockIdx.x * blockDim.x + threadIdx.x;
    if (i < e) atomicAdd(&deg[dst[i]], 1);
}

// single-block exclusive scan (n = 50000, 1024 threads, chunked Hillis-Steele)
__global__ void scan_kernel(const int* __restrict__ deg, int* __restrict__ off,
                            int* __restrict__ cur, int n) {
    __shared__ int sh[1024];
    __shared__ int carry;
    int tid = threadIdx.x;
    if (tid == 0) carry = 0;
    __syncthreads();
    for (int base = 0; base < n; base += 1024) {
        int i = base + tid;
        int v = (i < n) ? deg[i] : 0;
        sh[tid] = v;
        __syncthreads();
        #pragma unroll
        for (int s = 1; s < 1024; s <<= 1) {
            int t = (tid >= s) ? sh[tid - s] : 0;
            __syncthreads();
            sh[tid] += t;
            __syncthreads();
        }
        int excl = sh[tid] - v + carry;
        if (i < n) { off[i] = excl; cur[i] = excl; }
        __syncthreads();
        if (tid == 0) carry += sh[1023];
        __syncthreads();
    }
    if (tid == 0) off[n] = carry;
}

__global__ void fill_kernel(const int* __restrict__ src, const int* __restrict__ dst,
                            int* __restrict__ cur, int* __restrict__ csr, int e) {
    int i = blockIdx.x * blockDim.x + threadIdx.x;
    if (i < e) {
        int d = dst[i];
        int p = atomicAdd(&cur[d], 1);
        csr[p] = src[i];
    }
}

// ---------------------------------------------------------------------------
// Aggregation: hagg[n,:] = sum_{e in CSR[n]} h[src[e],:] / max(deg,1)
// One warp per node; each lane owns 8 columns (2 float4). 2-neighbor unroll.
// ---------------------------------------------------------------------------
__global__ void agg_kernel(const float* __restrict__ h, const int* __restrict__ off,
                           const int* __restrict__ csr, float* __restrict__ hagg, int n) {
    int warp = (blockIdx.x * blockDim.x + threadIdx.x) >> 5;
    int lane = threadIdx.x & 31;
    if (warp >= n) return;
    int beg = off[warp], end = off[warp + 1];

    float4 a0 = make_float4(0.f, 0.f, 0.f, 0.f);
    float4 a1 = make_float4(0.f, 0.f, 0.f, 0.f);

    int j = beg;
    for (; j + 1 < end; j += 2) {
        int s0 = csr[j], s1 = csr[j + 1];
        const float4* r0 = (const float4*)(h + (size_t)s0 * FDIM);
        const float4* r1 = (const float4*)(h + (size_t)s1 * FDIM);
        float4 x0 = r0[lane * 2], x1 = r0[lane * 2 + 1];
        float4 y0 = r1[lane * 2], y1 = r1[lane * 2 + 1];
        a0.x += x0.x + y0.x; a0.y += x0.y + y0.y; a0.z += x0.z + y0.z; a0.w += x0.w + y0.w;
        a1.x += x1.x + y1.x; a1.y += x1.y + y1.y; a1.z += x1.z + y1.z; a1.w += x1.w + y1.w;
    }
    if (j < end) {
        int s0 = csr[j];
        const float4* r0 = (const float4*)(h + (size_t)s0 * FDIM);
        float4 x0 = r0[lane * 2], x1 = r0[lane * 2 + 1];
        a0.x += x0.x; a0.y += x0.y; a0.z += x0.z; a0.w += x0.w;
        a1.x += x1.x; a1.y += x1.y; a1.z += x1.z; a1.w += x1.w;
    }
    int d = end - beg;
    float inv = 1.f / (float)(d > 0 ? d : 1);
    a0.x *= inv; a0.y *= inv; a0.z *= inv; a0.w *= inv;
    a1.x *= inv; a1.y *= inv; a1.z *= inv; a1.w *= inv;
    float4* w = (float4*)(hagg + (size_t)warp * FDIM);
    w[lane * 2]     = a0;
    w[lane * 2 + 1] = a1;
}

// ---------------------------------------------------------------------------
// Row L2 normalize: out[n,:] = in[n,:] / max(||in[n,:]||, 1e-6). Warp per row.
// ---------------------------------------------------------------------------
__global__ void norm_kernel(const float* __restrict__ in, float* __restrict__ out, int n) {
    int warp = (blockIdx.x * blockDim.x + threadIdx.x) >> 5;
    int lane = threadIdx.x & 31;
    if (warp >= n) return;
    const float4* r = (const float4*)(in + (size_t)warp * FDIM);
    float4 v0 = r[lane * 2], v1 = r[lane * 2 + 1];
    float s = v0.x * v0.x + v0.y * v0.y + v0.z * v0.z + v0.w * v0.w
            + v1.x * v1.x + v1.y * v1.y + v1.z * v1.z + v1.w * v1.w;
    #pragma unroll
    for (int o = 16; o; o >>= 1) s += __shfl_xor_sync(0xFFFFFFFFu, s, o);
    float inv = 1.f / fmaxf(sqrtf(s), 1e-6f);
    v0.x *= inv; v0.y *= inv; v0.z *= inv; v0.w *= inv;
    v1.x *= inv; v1.y *= inv; v1.z *= inv; v1.w *= inv;
    float4* w = (float4*)(out + (size_t)warp * FDIM);
    w[lane * 2]     = v0;
    w[lane * 2 + 1] = v1;
}

// ---------------------------------------------------------------------------
// Generic fp32 SGEMM:  C[m,n] = act( sum_k A[m,k] * B[n,k] + bias[n] ) + addin
//   A is split: k < K0 reads A0 (row = rowidx[m] if given, stride K0)
//               k >= K0 reads A1 (stride K-K0)
//   B is [Nn, K] row-major (i.e. we compute A @ B^T).
// Tiling: BM=128, BN=128, BK=8, 256 threads, 8x8 register blocking.
// Smem rows padded +4 floats -> conflict-free STS and 16B-aligned LDS.128.
// ---------------------------------------------------------------------------
#define BM 128
#define BN 128
#define BK 8
#define PAD 4

__global__ void __launch_bounds__(256)
gemm_kernel(const float* __restrict__ A0, int K0,
            const float* __restrict__ A1,
            const int* __restrict__ rowidx,
            const float* __restrict__ B,
            const float* __restrict__ bias,
            const float* __restrict__ addin,
            float* __restrict__ C,
            int M, int Nn, int K, int do_lrelu) {
    __shared__ float As[BK][BM + PAD];
    __shared__ float Bs[BK][BN + PAD];

    int tid = threadIdx.x;
    int block_m = blockIdx.y * BM;
    int block_n = blockIdx.x * BN;
    int tx = tid & 15;        // 0..15 -> 8 cols each
    int ty = tid >> 4;        // 0..15 -> 8 rows each
    int K1 = K - K0;

    float acc[8][8];
    #pragma unroll
    for (int i = 0; i < 8; i++)
        #pragma unroll
        for (int j = 0; j < 8; j++) acc[i][j] = 0.f;

    for (int k0 = 0; k0 < K; k0 += BK) {
        // ---- load A tile (BM x BK = 1024 elems, 4 per thread) ----
        for (int t = tid; t < BM * BK; t += 256) {
            int m = t >> 3, kk = t & 7;
            int gm = block_m + m, gk = k0 + kk;
            float v = 0.f;
            if (gm < M && gk < K) {
                if (gk < K0) {
                    int row = rowidx ? rowidx[gm] : gm;
                    v = A0[(size_t)row * K0 + gk];
                } else {
                    v = A1[(size_t)gm * K1 + (gk - K0)];
                }
            }
            As[kk][m] = v;
        }
        // ---- load B tile (BN x BK) ----
        for (int t = tid; t < BN * BK; t += 256) {
            int nn = t >> 3, kk = t & 7;
            int gn = block_n + nn, gk = k0 + kk;
            float v = 0.f;
            if (gn < Nn && gk < K) v = B[(size_t)gn * K + gk];
            Bs[kk][nn] = v;
        }
        __syncthreads();

        #pragma unroll
        for (int kk = 0; kk < BK; kk++) {
            float a[8], b[8];
            const float4* av = (const float4*)(&As[kk][ty * 8]);
            const float4* bv = (const float4*)(&Bs[kk][tx * 8]);
            float4 a0 = av[0], a1 = av[1];
            float4 b0 = bv[0], b1 = bv[1];
            a[0]=a0.x; a[1]=a0.y; a[2]=a0.z; a[3]=a0.w;
            a[4]=a1.x; a[5]=a1.y; a[6]=a1.z; a[7]=a1.w;
            b[0]=b0.x; b[1]=b0.y; b[2]=b0.z; b[3]=b0.w;
            b[4]=b1.x; b[5]=b1.y; b[6]=b1.z; b[7]=b1.w;
            #pragma unroll
            for (int i = 0; i < 8; i++)
                #pragma unroll
                for (int j = 0; j < 8; j++)
                    acc[i][j] = fmaf(a[i], b[j], acc[i][j]);
        }
        __syncthreads();
    }

    // ---- epilogue ----
    #pragma unroll
    for (int i = 0; i < 8; i++) {
        int gm = block_m + ty * 8 + i;
        if (gm >= M) continue;
        #pragma unroll
        for (int j = 0; j < 8; j++) {
            int gn = block_n + tx * 8 + j;
            if (gn >= Nn) continue;
            float v = acc[i][j] + bias[gn];
            if (do_lrelu) v = (v >= 0.f) ? v : 0.1f * v;
            if (addin) v += addin[(size_t)gm * Nn + gn];
            C[(size_t)gm * Nn + gn] = v;
        }
    }
}

// ---------------------------------------------------------------------------
// Host driver
// ---------------------------------------------------------------------------
static inline dim3 gemm_grid(int M, int Nn) {
    return dim3((Nn + BN - 1) / BN, (M + BM - 1) / BM);
}

extern "C" void kernel_launch(void* const* d_in, const int* in_sizes, int n_in,
                              void* d_out, int out_size) {
    const int*   node_ids = (const int*)  d_in[0];
    const float* content  = (const float*)d_in[1];
    const int*   src      = (const int*)  d_in[2];
    const int*   dst      = (const int*)  d_in[3];
    const float* emb      = (const float*)d_in[4];
    const float* W_exp    = (const float*)d_in[5];
    const float* b_exp    = (const float*)d_in[6];
    const float* W_p1     = (const float*)d_in[7];
    const float* b_p1     = (const float*)d_in[8];
    const float* W_p2     = (const float*)d_in[9];
    const float* b_p2     = (const float*)d_in[10];
    const float* W_conv   = (const float*)d_in[11];
    const float* b_conv   = (const float*)d_in[12];
    const float* Wo1      = (const float*)d_in[13];
    const float* bo1      = (const float*)d_in[14];
    const float* Wo2      = (const float*)d_in[15];
    const float* bo2      = (const float*)d_in[16];
    float* out = (float*)d_out;

    const int N = in_sizes[0];   // 50000
    const int E = in_sizes[2];   // 1000000

    float *p_c, *p_t, *p_h, *p_g;
    int *p_deg, *p_off, *p_cur, *p_csr;
    cudaGetSymbolAddress((void**)&p_c,   g_c);
    cudaGetSymbolAddress((void**)&p_t,   g_t);
    cudaGetSymbolAddress((void**)&p_h,   g_h);
    cudaGetSymbolAddress((void**)&p_g,   g_g);
    cudaGetSymbolAddress((void**)&p_deg, g_deg);
    cudaGetSymbolAddress((void**)&p_off, g_off);
    cudaGetSymbolAddress((void**)&p_cur, g_cur);
    cudaGetSymbolAddress((void**)&p_csr, g_csr);

    // ---- CSR build (reused across all 3 layers) ----
    zero_int_kernel<<<(N + 255) / 256, 256>>>(p_deg, N);
    deg_kernel<<<(E + 255) / 256, 256>>>(dst, p_deg, E);
    scan_kernel<<<1, 1024>>>(p_deg, p_off, p_cur, N);
    fill_kernel<<<(E + 255) / 256, 256>>>(src, dst, p_cur, p_csr, E);

    // ---- initial node representation ----
    // c = lrelu(content @ W_p1^T + b_p1)          [N,300]
    gemm_kernel<<<gemm_grid(N, NCDIM), 256>>>(content, NCDIM, nullptr, nullptr,
                                              W_p1, b_p1, nullptr, p_c,
                                              N, NCDIM, NCDIM, 1);
    // t = lrelu(c @ W_p2^T + b_p2)                [N,256]
    gemm_kernel<<<gemm_grid(N, FDIM), 256>>>(p_c, NCDIM, nullptr, nullptr,
                                             W_p2, b_p2, nullptr, p_t,
                                             N, FDIM, NCDIM, 1);
    // h = lrelu(emb[node_ids] @ W_exp^T + b_exp) + t
    gemm_kernel<<<gemm_grid(N, FDIM), 256>>>(emb, EDDIM, nullptr, node_ids,
                                             W_exp, b_exp, p_t, p_h,
                                             N, FDIM, EDDIM, 1);

    const int warp_blocks = (N * 32 + 255) / 256;

    // ---- 3 SAGE layers ----
    for (int i = 0; i < 3; i++) {
        // h_agg = segment_sum(h[src], dst) / max(deg, 1)
        agg_kernel<<<warp_blocks, 256>>>(p_h, p_off, p_csr, p_g, N);
        // t = (lrelu?)( [h, h_agg] @ W_conv[i]^T + b_conv[i] )
        gemm_kernel<<<gemm_grid(N, FDIM), 256>>>(p_h, FDIM, p_g, nullptr,
                                                 W_conv + (size_t)i * FDIM * 2 * FDIM,
                                                 b_conv + (size_t)i * FDIM,
                                                 nullptr, p_t,
                                                 N, FDIM, 2 * FDIM, (i < 2) ? 1 : 0);
        if (i < 2) {
            // row-normalize in place
            norm_kernel<<<warp_blocks, 256>>>(p_t, p_t, N);
            // g = lrelu(t @ Wo1[i]^T + bo1[i])
            gemm_kernel<<<gemm_grid(N, FDIM), 256>>>(p_t, FDIM, nullptr, nullptr,
                                                     Wo1 + (size_t)i * FDIM * FDIM,
                                                     bo1 + (size_t)i * FDIM,
                                                     nullptr, p_g,
                                                     N, FDIM, FDIM, 1);
            // h = g @ Wo2[i]^T + bo2[i]
            gemm_kernel<<<gemm_grid(N, FDIM), 256>>>(p_g, FDIM, nullptr, nullptr,
                                                     Wo2 + (size_t)i * FDIM * FDIM,
                                                     bo2 + (size_t)i * FDIM,
                                                     nullptr, p_h,
                                                     N, FDIM, FDIM, 0);
        } else {
            // final layer: normalized conv output goes straight to d_out
            norm_kernel<<<warp_blocks, 256>>>(p_t, out, N);
        }
    }
}

// round 9
// speedup vs baseline: 1.5486x; 1.5486x over previous
#include <cuda_runtime.h>
#include <cuda_bf16.h>
#include <math.h>
#include <stdint.h>

// ---------------------------------------------------------------------------
// Problem constants
// ---------------------------------------------------------------------------
#define NNODES 50000
#define NEDGES 1000000
#define FDIM   256
#define NCDIM  300
#define EDDIM  64

// Is the arch-specific (tcgen05-capable) target active for this compile pass?
#if defined(__CUDA_ARCH_FEAT_SM103_ALL) || defined(__CUDA_ARCH_FEAT_SM100_ALL) || defined(__CUDA_ARCH_FEAT_SM101_ALL)
#define HAVE_TCGEN05 1
#else
#define HAVE_TCGEN05 0
#endif

// ---------------------------------------------------------------------------
// Scratch (device globals — no allocation allowed)
// ---------------------------------------------------------------------------
__device__ float g_c[NNODES * NCDIM];
__device__ float g_t[NNODES * FDIM];
__device__ float g_h[NNODES * FDIM];
__device__ float g_g[NNODES * FDIM];
__device__ int   g_deg[NNODES];
__device__ int   g_off[NNODES + 1];
__device__ int   g_cur[NNODES];
__device__ int   g_csr[NEDGES];

// ---------------------------------------------------------------------------
// Common helpers
// ---------------------------------------------------------------------------
__device__ __forceinline__ uint32_t smem_u32(const void* p) {
    uint32_t a;
    asm("{ .reg .u64 t; cvta.to.shared.u64 t, %1; cvt.u32.u64 %0, t; }" : "=r"(a) : "l"(p));
    return a;
}

// split fp32 -> (hi bf16, lo bf16) packed pairs
__device__ __forceinline__ void split2(float x0, float x1, uint32_t& hp, uint32_t& lp) {
    __nv_bfloat16 h0 = __float2bfloat16(x0);
    __nv_bfloat16 h1 = __float2bfloat16(x1);
    __nv_bfloat16 l0 = __float2bfloat16(x0 - __bfloat162float(h0));
    __nv_bfloat16 l1 = __float2bfloat16(x1 - __bfloat162float(h1));
    hp = ((uint32_t)__bfloat16_as_ushort(h1) << 16) | __bfloat16_as_ushort(h0);
    lp = ((uint32_t)__bfloat16_as_ushort(l1) << 16) | __bfloat16_as_ushort(l0);
}

// ---------------------------------------------------------------------------
// mma.sync (base-target) helpers
// ---------------------------------------------------------------------------
__device__ __forceinline__ void ldsm_x4(uint32_t& r0, uint32_t& r1, uint32_t& r2, uint32_t& r3,
                                        uint32_t addr) {
    asm volatile("ldmatrix.sync.aligned.m8n8.x4.shared.b16 {%0,%1,%2,%3}, [%4];"
                 : "=r"(r0), "=r"(r1), "=r"(r2), "=r"(r3) : "r"(addr));
}
__device__ __forceinline__ void mma16816(float* c, uint32_t a0, uint32_t a1, uint32_t a2, uint32_t a3,
                                         uint32_t b0, uint32_t b1) {
    asm volatile("mma.sync.aligned.m16n8k16.row.col.f32.bf16.bf16.f32 "
                 "{%0,%1,%2,%3}, {%4,%5,%6,%7}, {%8,%9}, {%0,%1,%2,%3};"
                 : "+f"(c[0]), "+f"(c[1]), "+f"(c[2]), "+f"(c[3])
                 : "r"(a0), "r"(a1), "r"(a2), "r"(a3), "r"(b0), "r"(b1));
}

// ---------------------------------------------------------------------------
// tcgen05 helpers (only referenced under HAVE_TCGEN05; unused inline fns are
// not emitted in the base-target pass)
// ---------------------------------------------------------------------------
__device__ __forceinline__ uint32_t elect_one() {
    uint32_t pred;
    asm volatile("{\n\t.reg .pred p;\n\telect.sync _|p, 0xFFFFFFFF;\n\t"
                 "selp.b32 %0, 1, 0, p;\n\t}" : "=r"(pred));
    return pred;
}
__device__ __forceinline__ void mbar_init(uint32_t mbar, uint32_t cnt) {
    asm volatile("mbarrier.init.shared.b64 [%0], %1;" :: "r"(mbar), "r"(cnt) : "memory");
}
__device__ __forceinline__ void mbar_inval(uint32_t mbar) {
    asm volatile("mbarrier.inval.shared.b64 [%0];" :: "r"(mbar) : "memory");
}
__device__ __forceinline__ void mbar_wait_parity(uint32_t mbar, uint32_t parity) {
    uint32_t done;
    asm volatile("{\n\t.reg .pred p;\n\t"
                 "mbarrier.try_wait.parity.acquire.cta.shared::cta.b64 p, [%1], %2;\n\t"
                 "selp.b32 %0, 1, 0, p;\n\t}"
                 : "=r"(done) : "r"(mbar), "r"(parity) : "memory");
    if (!done) {
        asm volatile("{\n\t.reg .pred P1;\n\t"
                     "W1_%=:\n\t"
                     "mbarrier.try_wait.parity.acquire.cta.shared::cta.b64 P1, [%0], %1, 0x989680;\n\t"
                     "@P1 bra.uni W2_%=;\n\t"
                     "bra.uni W1_%=;\n\t"
                     "W2_%=:\n\t}"
                     :: "r"(mbar), "r"(parity) : "memory");
    }
}

#if HAVE_TCGEN05
__device__ __forceinline__ void tc_alloc(uint32_t sm_addr, uint32_t n) {
    asm volatile("tcgen05.alloc.cta_group::1.sync.aligned.shared::cta.b32 [%0], %1;"
                 :: "r"(sm_addr), "r"(n) : "memory");
}
__device__ __forceinline__ void tc_dealloc(uint32_t tm, uint32_t n) {
    asm volatile("tcgen05.dealloc.cta_group::1.sync.aligned.b32 %0, %1;" :: "r"(tm), "r"(n));
}
__device__ __forceinline__ void tc_relinq() {
    asm volatile("tcgen05.relinquish_alloc_permit.cta_group::1.sync.aligned;");
}
__device__ __forceinline__ void tc_commit(uint32_t mbar) {
    asm volatile("tcgen05.commit.cta_group::1.mbarrier::arrive::one.shared::cluster.b64 [%0];"
                 :: "r"(mbar) : "memory");
}
__device__ __forceinline__ void tc_fence_after() {
    asm volatile("tcgen05.fence::after_thread_sync;" ::: "memory");
}
__device__ __forceinline__ void tc_fence_before() {
    asm volatile("tcgen05.fence::before_thread_sync;" ::: "memory");
}
__device__ __forceinline__ void tc_wait_ld() {
    asm volatile("tcgen05.wait::ld.sync.aligned;" ::: "memory");
}
__device__ __forceinline__ void tc_ld_x32(uint32_t* r, uint32_t tmem) {
    asm volatile(
        "tcgen05.ld.sync.aligned.32x32b.x32.b32 "
        "{%0, %1, %2, %3, %4, %5, %6, %7, %8, %9, %10, %11, %12, %13, %14, %15, "
        " %16, %17, %18, %19, %20, %21, %22, %23, %24, %25, %26, %27, %28, %29, %30, %31}, [%32];"
        : "=r"(r[0]), "=r"(r[1]), "=r"(r[2]), "=r"(r[3]), "=r"(r[4]), "=r"(r[5]), "=r"(r[6]), "=r"(r[7]),
          "=r"(r[8]), "=r"(r[9]), "=r"(r[10]), "=r"(r[11]), "=r"(r[12]), "=r"(r[13]), "=r"(r[14]), "=r"(r[15]),
          "=r"(r[16]), "=r"(r[17]), "=r"(r[18]), "=r"(r[19]), "=r"(r[20]), "=r"(r[21]), "=r"(r[22]), "=r"(r[23]),
          "=r"(r[24]), "=r"(r[25]), "=r"(r[26]), "=r"(r[27]), "=r"(r[28]), "=r"(r[29]), "=r"(r[30]), "=r"(r[31])
        : "r"(tmem));
}
__device__ __forceinline__ void mma_bf16_ss(uint32_t d_tmem, uint64_t a_desc, uint64_t b_desc,
                                            uint32_t idesc, uint32_t enable) {
    asm volatile(
        "{\n\t.reg .pred p;\n\tsetp.ne.u32 p, %5, 0;\n\t"
        "tcgen05.mma.cta_group::1.kind::f16 [%0], %1, %2, %3, {%4, %4, %4, %4}, p;\n\t}"
        :: "r"(d_tmem), "l"(a_desc), "l"(b_desc), "r"(idesc), "r"(0u), "r"(enable)
        : "memory");
}
static __device__ __forceinline__ uint64_t make_desc_sw128(uint32_t addr) {
    uint64_t d = (uint64_t(2) << 61) | (uint64_t(1) << 46) | (uint64_t(64) << 32) | (uint64_t(1) << 16);
    return d | ((uint64_t)(addr >> 4) & 0x3FFF);
}
#define SW128(o) ((o) ^ (((o) >> 3) & 0x70))
#define IDESC_128x128 ((1u << 4) | (1u << 7) | (1u << 10) | ((128u / 8u) << 17) | ((128u / 16u) << 24))
#endif  // HAVE_TCGEN05

// ---------------------------------------------------------------------------
// Small utility kernels (unchanged, passing)
// ---------------------------------------------------------------------------
__global__ void zero_int_kernel(int* p, int n) {
    int i = blockIdx.x * blockDim.x + threadIdx.x;
    if (i < n) p[i] = 0;
}

__global__ void deg_kernel(const int* __restrict__ dst, int* __restrict__ deg, int e) {
    int i = blockIdx.x * blockDim.x + threadIdx.x;
    if (i < e) atomicAdd(&deg[dst[i]], 1);
}

__global__ void scan_kernel(const int* __restrict__ deg, int* __restrict__ off,
                            int* __restrict__ cur, int n) {
    __shared__ int sh[1024];
    __shared__ int carry;
    int tid = threadIdx.x;
    if (tid == 0) carry = 0;
    __syncthreads();
    for (int base = 0; base < n; base += 1024) {
        int i = base + tid;
        int v = (i < n) ? deg[i] : 0;
        sh[tid] = v;
        __syncthreads();
        #pragma unroll
        for (int s = 1; s < 1024; s <<= 1) {
            int t = (tid >= s) ? sh[tid - s] : 0;
            __syncthreads();
            sh[tid] += t;
            __syncthreads();
        }
        int excl = sh[tid] - v + carry;
        if (i < n) { off[i] = excl; cur[i] = excl; }
        __syncthreads();
        if (tid == 0) carry += sh[1023];
        __syncthreads();
    }
    if (tid == 0) off[n] = carry;
}

__global__ void fill_kernel(const int* __restrict__ src, const int* __restrict__ dst,
                            int* __restrict__ cur, int* __restrict__ csr, int e) {
    int i = blockIdx.x * blockDim.x + threadIdx.x;
    if (i < e) {
        int d = dst[i];
        int p = atomicAdd(&cur[d], 1);
        csr[p] = src[i];
    }
}

__global__ void agg_kernel(const float* __restrict__ h, const int* __restrict__ off,
                           const int* __restrict__ csr, float* __restrict__ hagg, int n) {
    int warp = (blockIdx.x * blockDim.x + threadIdx.x) >> 5;
    int lane = threadIdx.x & 31;
    if (warp >= n) return;
    int beg = off[warp], end = off[warp + 1];

    float4 a0 = make_float4(0.f, 0.f, 0.f, 0.f);
    float4 a1 = make_float4(0.f, 0.f, 0.f, 0.f);

    int j = beg;
    for (; j + 1 < end; j += 2) {
        int s0 = csr[j], s1 = csr[j + 1];
        const float4* r0 = (const float4*)(h + (size_t)s0 * FDIM);
        const float4* r1 = (const float4*)(h + (size_t)s1 * FDIM);
        float4 x0 = r0[lane * 2], x1 = r0[lane * 2 + 1];
        float4 y0 = r1[lane * 2], y1 = r1[lane * 2 + 1];
        a0.x += x0.x + y0.x; a0.y += x0.y + y0.y; a0.z += x0.z + y0.z; a0.w += x0.w + y0.w;
        a1.x += x1.x + y1.x; a1.y += x1.y + y1.y; a1.z += x1.z + y1.z; a1.w += x1.w + y1.w;
    }
    if (j < end) {
        int s0 = csr[j];
        const float4* r0 = (const float4*)(h + (size_t)s0 * FDIM);
        float4 x0 = r0[lane * 2], x1 = r0[lane * 2 + 1];
        a0.x += x0.x; a0.y += x0.y; a0.z += x0.z; a0.w += x0.w;
        a1.x += x1.x; a1.y += x1.y; a1.z += x1.z; a1.w += x1.w;
    }
    int d = end - beg;
    float inv = 1.f / (float)(d > 0 ? d : 1);
    a0.x *= inv; a0.y *= inv; a0.z *= inv; a0.w *= inv;
    a1.x *= inv; a1.y *= inv; a1.z *= inv; a1.w *= inv;
    float4* w = (float4*)(hagg + (size_t)warp * FDIM);
    w[lane * 2]     = a0;
    w[lane * 2 + 1] = a1;
}

__global__ void norm_kernel(const float* __restrict__ in, float* __restrict__ out, int n) {
    int warp = (blockIdx.x * blockDim.x + threadIdx.x) >> 5;
    int lane = threadIdx.x & 31;
    if (warp >= n) return;
    const float4* r = (const float4*)(in + (size_t)warp * FDIM);
    float4 v0 = r[lane * 2], v1 = r[lane * 2 + 1];
    float s = v0.x * v0.x + v0.y * v0.y + v0.z * v0.z + v0.w * v0.w
            + v1.x * v1.x + v1.y * v1.y + v1.z * v1.z + v1.w * v1.w;
    #pragma unroll
    for (int o = 16; o; o >>= 1) s += __shfl_xor_sync(0xFFFFFFFFu, s, o);
    float inv = 1.f / fmaxf(sqrtf(s), 1e-6f);
    v0.x *= inv; v0.y *= inv; v0.z *= inv; v0.w *= inv;
    v1.x *= inv; v1.y *= inv; v1.z *= inv; v1.w *= inv;
    float4* w = (float4*)(out + (size_t)warp * FDIM);
    w[lane * 2]     = v0;
    w[lane * 2 + 1] = v1;
}

// ---------------------------------------------------------------------------
// Split-bf16 tensor-core GEMM:
//   C[m,n] = act( sum_k A[m,k]*B[n,k] + bias[n] ) (+ addin)
// A split across A0 (k<K0, optional row gather) and A1 (k>=K0).
// D += Ah*Bh + Ah*Bl + Al*Bh  (fp32 accumulate). Tile 128x128, K-chunks of 64.
//
// Two bodies:
//   HAVE_TCGEN05: tcgen05 SS MMA with TMEM accumulator (sm_103a pass)
//   else:         mma.sync.m16n8k16 + ldmatrix (legal on base sm_103)
// ---------------------------------------------------------------------------

// --- shared-memory layout (bytes) ---
// tcgen05 path: [0]=tmem ptr, [8]=mbar, 4x 16KB SW128 tiles at 1024..66560
// mma path:     4x 18KB padded tiles (rows of 72 bf16 = 144B) at 1024..74752
#define OFF_TMEM 0
#define OFF_MBAR 8
#define TOF_AH   1024
#define TOF_AL   (1024 + 16384)
#define TOF_BH   (1024 + 32768)
#define TOF_BL   (1024 + 49152)
#define MOF_AH   1024
#define MOF_AL   (1024 + 18432)
#define MOF_BH   (1024 + 36864)
#define MOF_BL   (1024 + 55296)
#define DYN_SMEM (1024 + 73728)
#define ROWB     144   // padded row stride in bytes (72 bf16)

__global__ void __launch_bounds__(256)
tc_gemm(const float* __restrict__ A0, int K0,
        const float* __restrict__ A1,
        const int* __restrict__ rowidx,
        const float* __restrict__ B,
        const float* __restrict__ bias,
        const float* __restrict__ addin,
        float* __restrict__ C,
        int M, int Nn, int K, int do_lrelu) {
    extern __shared__ char sm[];
    uint32_t smb = smem_u32(sm);
    int tid = threadIdx.x;
    int wid = tid >> 5;
    int lane = tid & 31;
    int block_m = blockIdx.y * 128;
    int block_n = blockIdx.x * 128;
    int K1 = K - K0;
    int nchunk = (K + 63) >> 6;

#if HAVE_TCGEN05
    // ======================= tcgen05 path ==================================
    if (wid == 0) tc_alloc(smb + OFF_TMEM, 128);
    if (tid == 0) mbar_init(smb + OFF_MBAR, 1);
    __syncthreads();
    uint32_t tmem;
    asm volatile("ld.shared.b32 %0, [%1];" : "=r"(tmem) : "r"(smb + OFF_TMEM));

    const uint64_t dAh = make_desc_sw128(smb + TOF_AH);
    const uint64_t dAl = make_desc_sw128(smb + TOF_AL);
    const uint64_t dBh = make_desc_sw128(smb + TOF_BH);
    const uint64_t dBl = make_desc_sw128(smb + TOF_BL);

    uint32_t phase = 0;
    uint32_t first = 1;

    for (int ch = 0; ch < nchunk; ch++) {
        int k0 = ch << 6;
        for (int e = tid * 4; e < 128 * 64; e += 256 * 4) {
            int r = e >> 6, c = e & 63;
            int gm = block_m + r;
            float x[4];
            #pragma unroll
            for (int q = 0; q < 4; q++) {
                int gk = k0 + c + q;
                float v = 0.f;
                if (gm < M && gk < K) {
                    if (gk < K0) {
                        int row = rowidx ? rowidx[gm] : gm;
                        v = A0[(size_t)row * K0 + gk];
                    } else {
                        v = A1[(size_t)gm * K1 + (gk - K0)];
                    }
                }
                x[q] = v;
            }
            uint32_t hp[2], lp[2];
            split2(x[0], x[1], hp[0], lp[0]);
            split2(x[2], x[3], hp[1], lp[1]);
            int so = SW128(r * 128 + c * 2);
            *(uint2*)(sm + TOF_AH + so) = make_uint2(hp[0], hp[1]);
            *(uint2*)(sm + TOF_AL + so) = make_uint2(lp[0], lp[1]);
        }
        for (int e = tid * 4; e < 128 * 64; e += 256 * 4) {
            int r = e >> 6, c = e & 63;
            int gn = block_n + r;
            float x[4];
            #pragma unroll
            for (int q = 0; q < 4; q++) {
                int gk = k0 + c + q;
                x[q] = (gn < Nn && gk < K) ? B[(size_t)gn * K + gk] : 0.f;
            }
            uint32_t hp[2], lp[2];
            split2(x[0], x[1], hp[0], lp[0]);
            split2(x[2], x[3], hp[1], lp[1]);
            int so = SW128(r * 128 + c * 2);
            *(uint2*)(sm + TOF_BH + so) = make_uint2(hp[0], hp[1]);
            *(uint2*)(sm + TOF_BL + so) = make_uint2(lp[0], lp[1]);
        }
        asm volatile("fence.proxy.async.shared::cta;" ::: "memory");
        __syncthreads();

        if (wid == 0 && elect_one()) {
            #pragma unroll
            for (int k = 0; k < 4; k++) {
                mma_bf16_ss(tmem, dAh + k * 2, dBh + k * 2, IDESC_128x128, first ? 0u : 1u);
                first = 0;
            }
            #pragma unroll
            for (int k = 0; k < 4; k++)
                mma_bf16_ss(tmem, dAh + k * 2, dBl + k * 2, IDESC_128x128, 1u);
            #pragma unroll
            for (int k = 0; k < 4; k++)
                mma_bf16_ss(tmem, dAl + k * 2, dBh + k * 2, IDESC_128x128, 1u);
            tc_commit(smb + OFF_MBAR);
        }
        mbar_wait_parity(smb + OFF_MBAR, phase);
        phase ^= 1;
    }

    tc_fence_after();
    if (wid < 4) {
        int gm = block_m + wid * 32 + lane;
        int row_ok = (gm < M);
        #pragma unroll
        for (int cb = 0; cb < 4; cb++) {
            uint32_t regs[32];
            tc_ld_x32(regs, tmem + cb * 32);
            tc_wait_ld();
            if (row_ok) {
                int gn0 = block_n + cb * 32;
                #pragma unroll
                for (int j = 0; j < 32; j += 4) {
                    int gn = gn0 + j;
                    #pragma unroll
                    for (int q = 0; q < 4; q++) {
                        int g = gn + q;
                        if (g < Nn) {
                            float a = __uint_as_float(regs[j + q]) + bias[g];
                            if (do_lrelu) a = (a >= 0.f) ? a : 0.1f * a;
                            if (addin) a += addin[(size_t)gm * Nn + g];
                            C[(size_t)gm * Nn + g] = a;
                        }
                    }
                }
            }
        }
        tc_fence_before();
    }
    __syncthreads();
    if (tid == 0) mbar_inval(smb + OFF_MBAR);
    __syncthreads();
    if (wid == 0) { tc_relinq(); tc_dealloc(tmem, 128); }

#else
    // ======================= mma.sync fallback path ========================
    int wm = wid >> 2;   // 0..1  (m: 2 x 64)
    int wn = wid & 3;    // 0..3  (n: 4 x 32)
    int lrow = lane & 7;
    int lsel = lane >> 3;

    // per-lane ldmatrix row-address offsets (bytes into each tile region)
    uint32_t a_off[4], b_off[2];
    #pragma unroll
    for (int mf = 0; mf < 4; mf++)
        a_off[mf] = (uint32_t)((wm * 64 + mf * 16 + (lsel & 1) * 8 + lrow) * ROWB + (lsel >> 1) * 16);
    #pragma unroll
    for (int nb = 0; nb < 2; nb++)
        b_off[nb] = (uint32_t)((wn * 32 + nb * 16 + (lsel >> 1) * 8 + lrow) * ROWB + (lsel & 1) * 16);

    const uint32_t baseAH = smb + MOF_AH, baseAL = smb + MOF_AL;
    const uint32_t baseBH = smb + MOF_BH, baseBL = smb + MOF_BL;

    float acc[4][4][4];
    #pragma unroll
    for (int i = 0; i < 4; i++)
        #pragma unroll
        for (int j = 0; j < 4; j++)
            #pragma unroll
            for (int q = 0; q < 4; q++) acc[i][j][q] = 0.f;

    for (int ch = 0; ch < nchunk; ch++) {
        int k0 = ch << 6;
        if (ch) __syncthreads();  // previous chunk fully consumed

        // ---- stage A tile (128 x 64) hi/lo into padded rows ----
        for (int e = tid * 4; e < 128 * 64; e += 256 * 4) {
            int r = e >> 6, c = e & 63;
            int gm = block_m + r;
            float x[4];
            #pragma unroll
            for (int q = 0; q < 4; q++) {
                int gk = k0 + c + q;
                float v = 0.f;
                if (gm < M && gk < K) {
                    if (gk < K0) {
                        int row = rowidx ? rowidx[gm] : gm;
                        v = A0[(size_t)row * K0 + gk];
                    } else {
                        v = A1[(size_t)gm * K1 + (gk - K0)];
                    }
                }
                x[q] = v;
            }
            uint32_t hp[2], lp[2];
            split2(x[0], x[1], hp[0], lp[0]);
            split2(x[2], x[3], hp[1], lp[1]);
            int so = r * ROWB + c * 2;
            *(uint2*)(sm + MOF_AH + so) = make_uint2(hp[0], hp[1]);
            *(uint2*)(sm + MOF_AL + so) = make_uint2(lp[0], lp[1]);
        }
        // ---- stage B tile (128 x 64) ----
        for (int e = tid * 4; e < 128 * 64; e += 256 * 4) {
            int r = e >> 6, c = e & 63;
            int gn = block_n + r;
            float x[4];
            #pragma unroll
            for (int q = 0; q < 4; q++) {
                int gk = k0 + c + q;
                x[q] = (gn < Nn && gk < K) ? B[(size_t)gn * K + gk] : 0.f;
            }
            uint32_t hp[2], lp[2];
            split2(x[0], x[1], hp[0], lp[0]);
            split2(x[2], x[3], hp[1], lp[1]);
            int so = r * ROWB + c * 2;
            *(uint2*)(sm + MOF_BH + so) = make_uint2(hp[0], hp[1]);
            *(uint2*)(sm + MOF_BL + so) = make_uint2(lp[0], lp[1]);
        }
        __syncthreads();

        // ---- 4 K-steps of 16 ----
        #pragma unroll
        for (int ks = 0; ks < 4; ks++) {
            uint32_t kb2 = (uint32_t)(ks * 16 * 2);
            uint32_t ah[4][4], al[4][4], bh[4][2], bl[4][2];
            #pragma unroll
            for (int mf = 0; mf < 4; mf++) {
                ldsm_x4(ah[mf][0], ah[mf][1], ah[mf][2], ah[mf][3], baseAH + a_off[mf] + kb2);
                ldsm_x4(al[mf][0], al[mf][1], al[mf][2], al[mf][3], baseAL + a_off[mf] + kb2);
            }
            #pragma unroll
            for (int nb = 0; nb < 2; nb++) {
                uint32_t r0, r1, r2, r3;
                ldsm_x4(r0, r1, r2, r3, baseBH + b_off[nb] + kb2);
                bh[2 * nb][0] = r0; bh[2 * nb][1] = r1;
                bh[2 * nb + 1][0] = r2; bh[2 * nb + 1][1] = r3;
                ldsm_x4(r0, r1, r2, r3, baseBL + b_off[nb] + kb2);
                bl[2 * nb][0] = r0; bl[2 * nb][1] = r1;
                bl[2 * nb + 1][0] = r2; bl[2 * nb + 1][1] = r3;
            }
            #pragma unroll
            for (int mf = 0; mf < 4; mf++) {
                #pragma unroll
                for (int nf = 0; nf < 4; nf++) {
                    mma16816(acc[mf][nf], ah[mf][0], ah[mf][1], ah[mf][2], ah[mf][3],
                             bh[nf][0], bh[nf][1]);
                    mma16816(acc[mf][nf], ah[mf][0], ah[mf][1], ah[mf][2], ah[mf][3],
                             bl[nf][0], bl[nf][1]);
                    mma16816(acc[mf][nf], al[mf][0], al[mf][1], al[mf][2], al[mf][3],
                             bh[nf][0], bh[nf][1]);
                }
            }
        }
    }

    // ---- epilogue ----
    int gr = lane >> 2;
    int gc = 2 * (lane & 3);
    #pragma unroll
    for (int mf = 0; mf < 4; mf++) {
        #pragma unroll
        for (int half = 0; half < 2; half++) {
            int gm = block_m + wm * 64 + mf * 16 + gr + half * 8;
            if (gm >= M) continue;
            #pragma unroll
            for (int nf = 0; nf < 4; nf++) {
                int gn = block_n + wn * 32 + nf * 8 + gc;
                float v0 = acc[mf][nf][half * 2 + 0];
                float v1 = acc[mf][nf][half * 2 + 1];
                if (gn < Nn) {
                    float a = v0 + bias[gn];
                    if (do_lrelu) a = (a >= 0.f) ? a : 0.1f * a;
                    if (addin) a += addin[(size_t)gm * Nn + gn];
                    if (gn + 1 < Nn) {
                        float b = v1 + bias[gn + 1];
                        if (do_lrelu) b = (b >= 0.f) ? b : 0.1f * b;
                        if (addin) b += addin[(size_t)gm * Nn + gn + 1];
                        *(float2*)(C + (size_t)gm * Nn + gn) = make_float2(a, b);
                    } else {
                        C[(size_t)gm * Nn + gn] = a;
                    }
                }
            }
        }
    }
#endif
}

// ---------------------------------------------------------------------------
// Host driver
// ---------------------------------------------------------------------------
static inline dim3 tc_grid(int M, int Nn) {
    return dim3((Nn + 127) / 128, (M + 127) / 128);
}

extern "C" void kernel_launch(void* const* d_in, const int* in_sizes, int n_in,
                              void* d_out, int out_size) {
    const int*   node_ids = (const int*)  d_in[0];
    const float* content  = (const float*)d_in[1];
    const int*   src      = (const int*)  d_in[2];
    const int*   dst      = (const int*)  d_in[3];
    const float* emb      = (const float*)d_in[4];
    const float* W_exp    = (const float*)d_in[5];
    const float* b_exp    = (const float*)d_in[6];
    const float* W_p1     = (const float*)d_in[7];
    const float* b_p1     = (const float*)d_in[8];
    const float* W_p2     = (const float*)d_in[9];
    const float* b_p2     = (const float*)d_in[10];
    const float* W_conv   = (const float*)d_in[11];
    const float* b_conv   = (const float*)d_in[12];
    const float* Wo1      = (const float*)d_in[13];
    const float* bo1      = (const float*)d_in[14];
    const float* Wo2      = (const float*)d_in[15];
    const float* bo2      = (const float*)d_in[16];
    float* out = (float*)d_out;

    const int N = in_sizes[0];
    const int E = in_sizes[2];

    float *p_c, *p_t, *p_h, *p_g;
    int *p_deg, *p_off, *p_cur, *p_csr;
    cudaGetSymbolAddress((void**)&p_c,   g_c);
    cudaGetSymbolAddress((void**)&p_t,   g_t);
    cudaGetSymbolAddress((void**)&p_h,   g_h);
    cudaGetSymbolAddress((void**)&p_g,   g_g);
    cudaGetSymbolAddress((void**)&p_deg, g_deg);
    cudaGetSymbolAddress((void**)&p_off, g_off);
    cudaGetSymbolAddress((void**)&p_cur, g_cur);
    cudaGetSymbolAddress((void**)&p_csr, g_csr);

    cudaFuncSetAttribute(tc_gemm, cudaFuncAttributeMaxDynamicSharedMemorySize, DYN_SMEM);

    // ---- CSR build ----
    zero_int_kernel<<<(N + 255) / 256, 256>>>(p_deg, N);
    deg_kernel<<<(E + 255) / 256, 256>>>(dst, p_deg, E);
    scan_kernel<<<1, 1024>>>(p_deg, p_off, p_cur, N);
    fill_kernel<<<(E + 255) / 256, 256>>>(src, dst, p_cur, p_csr, E);

    // ---- initial node representation ----
    tc_gemm<<<tc_grid(N, NCDIM), 256, DYN_SMEM>>>(content, NCDIM, nullptr, nullptr,
                                                  W_p1, b_p1, nullptr, p_c,
                                                  N, NCDIM, NCDIM, 1);
    tc_gemm<<<tc_grid(N, FDIM), 256, DYN_SMEM>>>(p_c, NCDIM, nullptr, nullptr,
                                                 W_p2, b_p2, nullptr, p_t,
                                                 N, FDIM, NCDIM, 1);
    tc_gemm<<<tc_grid(N, FDIM), 256, DYN_SMEM>>>(emb, EDDIM, nullptr, node_ids,
                                                 W_exp, b_exp, p_t, p_h,
                                                 N, FDIM, EDDIM, 1);

    const int warp_blocks = (N * 32 + 255) / 256;

    // ---- 3 SAGE layers ----
    for (int i = 0; i < 3; i++) {
        agg_kernel<<<warp_blocks, 256>>>(p_h, p_off, p_csr, p_g, N);
        tc_gemm<<<tc_grid(N, FDIM), 256, DYN_SMEM>>>(p_h, FDIM, p_g, nullptr,
                                                     W_conv + (size_t)i * FDIM * 2 * FDIM,
                                                     b_conv + (size_t)i * FDIM,
                                                     nullptr, p_t,
                                                     N, FDIM, 2 * FDIM, (i < 2) ? 1 : 0);
        if (i < 2) {
            norm_kernel<<<warp_blocks, 256>>>(p_t, p_t, N);
            tc_gemm<<<tc_grid(N, FDIM), 256, DYN_SMEM>>>(p_t, FDIM, nullptr, nullptr,
                                                         Wo1 + (size_t)i * FDIM * FDIM,
                                                         bo1 + (size_t)i * FDIM,
                                                         nullptr, p_g,
                                                         N, FDIM, FDIM, 1);
            tc_gemm<<<tc_grid(N, FDIM), 256, DYN_SMEM>>>(p_g, FDIM, nullptr, nullptr,
                                                         Wo2 + (size_t)i * FDIM * FDIM,
                                                         bo2 + (size_t)i * FDIM,
                                                         nullptr, p_h,
                                                         N, FDIM, FDIM, 0);
        } else {
            norm_kernel<<<warp_blocks, 256>>>(p_t, out, N);
        }
    }
}

// round 13
// speedup vs baseline: 2.5118x; 1.6220x over previous
#include <cuda_runtime.h>
#include <cuda_bf16.h>
#include <stdint.h>
#include <math.h>

// ---------------------------------------------------------------------------
// Problem constants
// ---------------------------------------------------------------------------
#define NNODES 50000
#define NEDGES 1000000
#define FD     256
#define NC     300
#define NCP    320   // NC padded to multiple of 32
#define ED     64

typedef unsigned short u16;
typedef unsigned int   u32;

// ---------------------------------------------------------------------------
// Scratch (device globals — no allocation allowed)
// All activations/weights stored as split bf16 "planes": hi plane + lo plane,
// value = float(hi) + float(lo)  (≈ fp32 with 16-bit mantissa, err ~2^-17).
// ---------------------------------------------------------------------------
__device__ u16 g_cont_h[NNODES * NCP], g_cont_l[NNODES * NCP];
__device__ u16 g_c_h[NNODES * NCP],    g_c_l[NNODES * NCP];
__device__ u16 g_e_h[NNODES * ED],     g_e_l[NNODES * ED];
__device__ u16 g_h_h[NNODES * FD],     g_h_l[NNODES * FD];
__device__ u16 g_t_h[NNODES * FD],     g_t_l[NNODES * FD];
__device__ u16 g_g_h[NNODES * FD],     g_g_l[NNODES * FD];

// weight-plane offsets (u16 elements)
#define WP1   0
#define WP2   96000              // + 300*320
#define WEXP  177920             // + 256*320
#define WCONV 194304             // + 256*64
#define WO1   587520             // + 3*256*512
#define WO2   718592             // + 2*256*256
#define WTOT  849664             // + 2*256*256
__device__ u16 g_w_h[WTOT], g_w_l[WTOT];

__device__ int g_deg[NNODES];
__device__ int g_off[NNODES + 1];
__device__ int g_cur[NNODES];
__device__ int g_csr[NEDGES];

// ---------------------------------------------------------------------------
// Helpers
// ---------------------------------------------------------------------------
__device__ __forceinline__ u32 smem_u32(const void* p) {
    u32 a;
    asm("{ .reg .u64 t; cvta.to.shared.u64 t, %1; cvt.u32.u64 %0, t; }" : "=r"(a) : "l"(p));
    return a;
}
__device__ __forceinline__ void splitf(float x, u16& h, u16& l) {
    __nv_bfloat16 hb = __float2bfloat16(x);
    float hf = __bfloat162float(hb);
    __nv_bfloat16 lb = __float2bfloat16(x - hf);
    h = __bfloat16_as_ushort(hb);
    l = __bfloat16_as_ushort(lb);
}
// bf16 bits -> fp32 (low / high half of a packed u32) — pure bit ops
__device__ __forceinline__ float bflo(u32 u) { return __uint_as_float(u << 16); }
__device__ __forceinline__ float bfhi(u32 u) { return __uint_as_float(u & 0xFFFF0000u); }

__device__ __forceinline__ void ldsm_x4(u32& r0, u32& r1, u32& r2, u32& r3, u32 addr) {
    asm volatile("ldmatrix.sync.aligned.m8n8.x4.shared.b16 {%0,%1,%2,%3}, [%4];"
                 : "=r"(r0), "=r"(r1), "=r"(r2), "=r"(r3) : "r"(addr));
}
__device__ __forceinline__ void mma16816(float* c, u32 a0, u32 a1, u32 a2, u32 a3,
                                         u32 b0, u32 b1) {
    asm volatile("mma.sync.aligned.m16n8k16.row.col.f32.bf16.bf16.f32 "
                 "{%0,%1,%2,%3}, {%4,%5,%6,%7}, {%8,%9}, {%0,%1,%2,%3};"
                 : "+f"(c[0]), "+f"(c[1]), "+f"(c[2]), "+f"(c[3])
                 : "r"(a0), "r"(a1), "r"(a2), "r"(a3), "r"(b0), "r"(b1));
}
// cp.async with zfill mask: pointer is ALWAYS in-bounds (caller clamps row),
// src-size=0 only zero-fills.
__device__ __forceinline__ void cp16(u32 dst, const void* src, int valid) {
    asm volatile("cp.async.cg.shared.global [%0], [%1], 16, %2;"
                 :: "r"(dst), "l"(src), "r"(valid ? 16 : 0));
}

// ---------------------------------------------------------------------------
// Prep: split fp32 matrix (rows x sc) into hi/lo planes (rows x dc, zero-pad),
// optional row gather.
// ---------------------------------------------------------------------------
__global__ void split_kernel(const float* __restrict__ src, int rows, int sc, int dc,
                             u16* __restrict__ dh, u16* __restrict__ dl,
                             const int* __restrict__ gather) {
    int i = blockIdx.x * blockDim.x + threadIdx.x;
    if (i >= rows * dc) return;
    int r = i / dc, c = i - r * dc;
    float v = 0.f;
    if (c < sc) {
        int rr = gather ? gather[r] : r;
        v = src[(size_t)rr * sc + c];
    }
    u16 h, l;
    splitf(v, h, l);
    dh[i] = h;
    dl[i] = l;
}

// ---------------------------------------------------------------------------
// CSR build kernels
// ---------------------------------------------------------------------------
__global__ void zero_int_kernel(int* p, int n) {
    int i = blockIdx.x * blockDim.x + threadIdx.x;
    if (i < n) p[i] = 0;
}
__global__ void deg_kernel(const int* __restrict__ dst, int* __restrict__ deg, int e) {
    int i = blockIdx.x * blockDim.x + threadIdx.x;
    if (i < e) atomicAdd(&deg[dst[i]], 1);
}
__global__ void scan_kernel(const int* __restrict__ deg, int* __restrict__ off,
                            int* __restrict__ cur, int n) {
    __shared__ int sh[1024];
    __shared__ int carry;
    int tid = threadIdx.x;
    if (tid == 0) carry = 0;
    __syncthreads();
    for (int base = 0; base < n; base += 1024) {
        int i = base + tid;
        int v = (i < n) ? deg[i] : 0;
        sh[tid] = v;
        __syncthreads();
        #pragma unroll
        for (int s = 1; s < 1024; s <<= 1) {
            int t = (tid >= s) ? sh[tid - s] : 0;
            __syncthreads();
            sh[tid] += t;
            __syncthreads();
        }
        int excl = sh[tid] - v + carry;
        if (i < n) { off[i] = excl; cur[i] = excl; }
        __syncthreads();
        if (tid == 0) carry += sh[1023];
        __syncthreads();
    }
    if (tid == 0) off[n] = carry;
}
__global__ void fill_kernel(const int* __restrict__ src, const int* __restrict__ dst,
                            int* __restrict__ cur, int* __restrict__ csr, int e) {
    int i = blockIdx.x * blockDim.x + threadIdx.x;
    if (i < e) {
        int d = dst[i];
        int p = atomicAdd(&cur[d], 1);
        csr[p] = src[i];
    }
}

// ---------------------------------------------------------------------------
// Aggregation on planes: o[n,:] = (sum_{s in CSR[n]} h[s,:]) / max(deg,1)
// Warp per node, lane owns 8 columns. 2-neighbor unroll.
// ---------------------------------------------------------------------------
#define ACC8(hv, lv)                                                   \
    { acc[0] += bflo(hv.x) + bflo(lv.x); acc[1] += bfhi(hv.x) + bfhi(lv.x); \
      acc[2] += bflo(hv.y) + bflo(lv.y); acc[3] += bfhi(hv.y) + bfhi(lv.y); \
      acc[4] += bflo(hv.z) + bflo(lv.z); acc[5] += bfhi(hv.z) + bfhi(lv.z); \
      acc[6] += bflo(hv.w) + bflo(lv.w); acc[7] += bfhi(hv.w) + bfhi(lv.w); }

__global__ void agg_pl(const u16* __restrict__ hh, const u16* __restrict__ hl,
                       const int* __restrict__ off, const int* __restrict__ csr,
                       u16* __restrict__ oh, u16* __restrict__ ol, int n) {
    int w = (blockIdx.x * blockDim.x + threadIdx.x) >> 5;
    int lane = threadIdx.x & 31;
    if (w >= n) return;
    int beg = off[w], end = off[w + 1];
    size_t lo8 = (size_t)lane * 8;

    float acc[8];
    #pragma unroll
    for (int i = 0; i < 8; i++) acc[i] = 0.f;

    int j = beg;
    for (; j + 1 < end; j += 2) {
        int s0 = csr[j], s1 = csr[j + 1];
        uint4 h0 = *(const uint4*)(hh + (size_t)s0 * FD + lo8);
        uint4 l0 = *(const uint4*)(hl + (size_t)s0 * FD + lo8);
        uint4 h1 = *(const uint4*)(hh + (size_t)s1 * FD + lo8);
        uint4 l1 = *(const uint4*)(hl + (size_t)s1 * FD + lo8);
        ACC8(h0, l0);
        ACC8(h1, l1);
    }
    if (j < end) {
        int s0 = csr[j];
        uint4 h0 = *(const uint4*)(hh + (size_t)s0 * FD + lo8);
        uint4 l0 = *(const uint4*)(hl + (size_t)s0 * FD + lo8);
        ACC8(h0, l0);
    }
    int d = end - beg;
    float inv = 1.f / (float)(d > 0 ? d : 1);

    u16 sh[8], sl[8];
    #pragma unroll
    for (int i = 0; i < 8; i++) splitf(acc[i] * inv, sh[i], sl[i]);
    uint4 vh, vl;
    vh.x = sh[0] | ((u32)sh[1] << 16); vl.x = sl[0] | ((u32)sl[1] << 16);
    vh.y = sh[2] | ((u32)sh[3] << 16); vl.y = sl[2] | ((u32)sl[3] << 16);
    vh.z = sh[4] | ((u32)sh[5] << 16); vl.z = sl[4] | ((u32)sl[5] << 16);
    vh.w = sh[6] | ((u32)sh[7] << 16); vl.w = sl[6] | ((u32)sl[7] << 16);
    *(uint4*)(oh + (size_t)w * FD + lo8) = vh;
    *(uint4*)(ol + (size_t)w * FD + lo8) = vl;
}

// ---------------------------------------------------------------------------
// Row L2 normalize on planes. If of != null, write fp32 there instead.
// ---------------------------------------------------------------------------
__global__ void norm_pl(const u16* __restrict__ th, const u16* __restrict__ tl,
                        u16* __restrict__ oh, u16* __restrict__ ol,
                        float* __restrict__ of, int n) {
    int w = (blockIdx.x * blockDim.x + threadIdx.x) >> 5;
    int lane = threadIdx.x & 31;
    if (w >= n) return;
    size_t lo8 = (size_t)lane * 8;
    uint4 hv = *(const uint4*)(th + (size_t)w * FD + lo8);
    uint4 lv = *(const uint4*)(tl + (size_t)w * FD + lo8);
    float x[8];
    x[0] = bflo(hv.x) + bflo(lv.x); x[1] = bfhi(hv.x) + bfhi(lv.x);
    x[2] = bflo(hv.y) + bflo(lv.y); x[3] = bfhi(hv.y) + bfhi(lv.y);
    x[4] = bflo(hv.z) + bflo(lv.z); x[5] = bfhi(hv.z) + bfhi(lv.z);
    x[6] = bflo(hv.w) + bflo(lv.w); x[7] = bfhi(hv.w) + bfhi(lv.w);
    float s = 0.f;
    #pragma unroll
    for (int i = 0; i < 8; i++) s += x[i] * x[i];
    #pragma unroll
    for (int o = 16; o; o >>= 1) s += __shfl_xor_sync(0xFFFFFFFFu, s, o);
    float inv = 1.f / fmaxf(sqrtf(s), 1e-6f);
    #pragma unroll
    for (int i = 0; i < 8; i++) x[i] *= inv;

    if (of) {
        float4 a = make_float4(x[0], x[1], x[2], x[3]);
        float4 b = make_float4(x[4], x[5], x[6], x[7]);
        *(float4*)(of + (size_t)w * FD + lo8)     = a;
        *(float4*)(of + (size_t)w * FD + lo8 + 4) = b;
    } else {
        u16 sh[8], sl[8];
        #pragma unroll
        for (int i = 0; i < 8; i++) splitf(x[i], sh[i], sl[i]);
        uint4 vh, vl;
        vh.x = sh[0] | ((u32)sh[1] << 16); vl.x = sl[0] | ((u32)sl[1] << 16);
        vh.y = sh[2] | ((u32)sh[3] << 16); vl.y = sl[2] | ((u32)sl[3] << 16);
        vh.z = sh[4] | ((u32)sh[5] << 16); vl.z = sl[4] | ((u32)sl[5] << 16);
        vh.w = sh[6] | ((u32)sh[7] << 16); vl.w = sl[6] | ((u32)sl[7] << 16);
        *(uint4*)(oh + (size_t)w * FD + lo8) = vh;
        *(uint4*)(ol + (size_t)w * FD + lo8) = vl;
    }
}

// ---------------------------------------------------------------------------
// Plane GEMM (split-bf16, 3-pass: AhBh + AhBl + AlBh, fp32 accum):
//   C[m,n] = act( sum_k A[m,k]*B[n,k] + bias[n] ) (+ addin) -> hi/lo planes
// A concat: k < K0 from (Ah,Al) stride K0; k >= K0 from (A2h,A2l) stride K-K0.
// B planes stride K. Tile 128x128, K-chunk 32, 2-stage cp.async pipeline.
// SMEM tiles: 128 rows x 32 bf16, row stride 80B (conflict-free ldmatrix).
// OOB rows: pointer clamped in-bounds, cp.async zfill writes zeros.
// ---------------------------------------------------------------------------
#define TS   10240            // one tile: 128*80 bytes
#define STG  (4 * TS)         // Ah,Al,Bh,Bl per stage
#define GSM  (2 * STG)        // 81920 bytes dynamic smem
#define ROWB 80

__global__ void __launch_bounds__(256)
pgemm(const u16* __restrict__ Ah, const u16* __restrict__ Al,
      const u16* __restrict__ A2h, const u16* __restrict__ A2l, int K0,
      const u16* __restrict__ Bh, const u16* __restrict__ Bl,
      const float* __restrict__ bias,
      const u16* __restrict__ addh, const u16* __restrict__ addl,
      u16* __restrict__ Ch, u16* __restrict__ Cl, int Cs,
      int M, int Nn, int K, int do_lrelu) {
    extern __shared__ char smc[];
    u32 smb = smem_u32(smc);
    int tid = threadIdx.x;
    int wid = tid >> 5;
    int lane = tid & 31;
    int block_m = blockIdx.y * 128;
    int block_n = blockIdx.x * 128;
    int nchunk = K >> 5;

    // ---- staging lambda: chunk ch -> stage s ----
    auto stage = [&](int s, int ch) {
        int k0 = ch << 5;
        const u16 *aH, *aL;
        int ak, astr;
        if (k0 < K0) { aH = Ah;  aL = Al;  ak = k0;      astr = K0; }
        else         { aH = A2h; aL = A2l; ak = k0 - K0; astr = K - K0; }
        for (int e = tid; e < 2048; e += 256) {
            int tile = e >> 9;
            int r = (e >> 2) & 127;
            int c = e & 3;
            const u16* g;
            int valid;
            if (tile < 2) {
                int gm = block_m + r;
                valid = gm < M;
                int gms = valid ? gm : (M - 1);   // clamp: pointer always in-bounds
                g = (tile ? aL : aH) + (size_t)gms * astr + ak + c * 8;
            } else {
                int gn = block_n + r;
                valid = gn < Nn;
                int gns = valid ? gn : (Nn - 1);
                g = (tile == 3 ? Bl : Bh) + (size_t)gns * K + k0 + c * 8;
            }
            u32 d = smb + s * STG + tile * TS + r * ROWB + c * 16;
            cp16(d, g, valid);
        }
    };

    // ---- per-lane ldmatrix offsets ----
    int wm = wid >> 2;   // 0..1
    int wn = wid & 3;    // 0..3
    int lrow = lane & 7;
    int lsel = lane >> 3;
    u32 a_off[4], b_off[2];
    #pragma unroll
    for (int mf = 0; mf < 4; mf++)
        a_off[mf] = (u32)((wm * 64 + mf * 16 + (lsel & 1) * 8 + lrow) * ROWB + (lsel >> 1) * 16);
    #pragma unroll
    for (int nb = 0; nb < 2; nb++)
        b_off[nb] = (u32)((wn * 32 + nb * 16 + (lsel >> 1) * 8 + lrow) * ROWB + (lsel & 1) * 16);

    float acc[4][4][4];
    #pragma unroll
    for (int i = 0; i < 4; i++)
        #pragma unroll
        for (int j = 0; j < 4; j++)
            #pragma unroll
            for (int q = 0; q < 4; q++) acc[i][j][q] = 0.f;

    // ---- pipeline ----
    stage(0, 0);
    asm volatile("cp.async.commit_group;");

    for (int ch = 0; ch < nchunk; ch++) {
        if (ch + 1 < nchunk) {
            stage((ch + 1) & 1, ch + 1);
            asm volatile("cp.async.commit_group;");
            asm volatile("cp.async.wait_group 1;");
        } else {
            asm volatile("cp.async.wait_group 0;");
        }
        __syncthreads();

        int s = ch & 1;
        u32 bAH = smb + s * STG;
        u32 bAL = bAH + TS;
        u32 bBH = bAH + 2 * TS;
        u32 bBL = bAH + 3 * TS;

        #pragma unroll
        for (int ks = 0; ks < 2; ks++) {
            u32 kb = (u32)(ks * 32);
            u32 ah[4][4], al[4][4], bh[4][2], bl[4][2];
            #pragma unroll
            for (int mf = 0; mf < 4; mf++) {
                ldsm_x4(ah[mf][0], ah[mf][1], ah[mf][2], ah[mf][3], bAH + a_off[mf] + kb);
                ldsm_x4(al[mf][0], al[mf][1], al[mf][2], al[mf][3], bAL + a_off[mf] + kb);
            }
            #pragma unroll
            for (int nb = 0; nb < 2; nb++) {
                u32 r0, r1, r2, r3;
                ldsm_x4(r0, r1, r2, r3, bBH + b_off[nb] + kb);
                bh[2 * nb][0] = r0; bh[2 * nb][1] = r1;
                bh[2 * nb + 1][0] = r2; bh[2 * nb + 1][1] = r3;
                ldsm_x4(r0, r1, r2, r3, bBL + b_off[nb] + kb);
                bl[2 * nb][0] = r0; bl[2 * nb][1] = r1;
                bl[2 * nb + 1][0] = r2; bl[2 * nb + 1][1] = r3;
            }
            #pragma unroll
            for (int mf = 0; mf < 4; mf++) {
                #pragma unroll
                for (int nf = 0; nf < 4; nf++) {
                    mma16816(acc[mf][nf], ah[mf][0], ah[mf][1], ah[mf][2], ah[mf][3],
                             bh[nf][0], bh[nf][1]);
                    mma16816(acc[mf][nf], ah[mf][0], ah[mf][1], ah[mf][2], ah[mf][3],
                             bl[nf][0], bl[nf][1]);
                    mma16816(acc[mf][nf], al[mf][0], al[mf][1], al[mf][2], al[mf][3],
                             bh[nf][0], bh[nf][1]);
                }
            }
        }
        __syncthreads();
    }

    // ---- epilogue: bias + lrelu + addin, split to hi/lo planes ----
    int gr = lane >> 2;
    int gc = 2 * (lane & 3);
    #pragma unroll
    for (int mf = 0; mf < 4; mf++) {
        #pragma unroll
        for (int half = 0; half < 2; half++) {
            int gm = block_m + wm * 64 + mf * 16 + gr + half * 8;
            if (gm >= M) continue;
            #pragma unroll
            for (int nf = 0; nf < 4; nf++) {
                int gn = block_n + wn * 32 + nf * 8 + gc;
                if (gn >= Nn) continue;   // Nn even, gn even -> gn+1 < Nn too
                float a0 = acc[mf][nf][half * 2 + 0] + bias[gn];
                float a1 = acc[mf][nf][half * 2 + 1] + bias[gn + 1];
                if (do_lrelu) {
                    a0 = (a0 >= 0.f) ? a0 : 0.1f * a0;
                    a1 = (a1 >= 0.f) ? a1 : 0.1f * a1;
                }
                if (addh) {
                    size_t ai = (size_t)gm * Nn + gn;
                    u32 avh = *(const u32*)(addh + ai);
                    u32 avl = *(const u32*)(addl + ai);
                    a0 += bflo(avh) + bflo(avl);
                    a1 += bfhi(avh) + bfhi(avl);
                }
                u16 h0, l0, h1, l1;
                splitf(a0, h0, l0);
                splitf(a1, h1, l1);
                size_t ci = (size_t)gm * Cs + gn;
                *(u32*)(Ch + ci) = h0 | ((u32)h1 << 16);
                *(u32*)(Cl + ci) = l0 | ((u32)l1 << 16);
            }
        }
    }
}

// ---------------------------------------------------------------------------
// Host driver
// ---------------------------------------------------------------------------
static inline dim3 pg_grid(int M, int Nn) {
    return dim3((Nn + 127) / 128, (M + 127) / 128);
}

extern "C" void kernel_launch(void* const* d_in, const int* in_sizes, int n_in,
                              void* d_out, int out_size) {
    const int*   node_ids = (const int*)  d_in[0];
    const float* content  = (const float*)d_in[1];
    const int*   src      = (const int*)  d_in[2];
    const int*   dst      = (const int*)  d_in[3];
    const float* emb      = (const float*)d_in[4];
    const float* W_exp    = (const float*)d_in[5];
    const float* b_exp    = (const float*)d_in[6];
    const float* W_p1     = (const float*)d_in[7];
    const float* b_p1     = (const float*)d_in[8];
    const float* W_p2     = (const float*)d_in[9];
    const float* b_p2     = (const float*)d_in[10];
    const float* W_conv   = (const float*)d_in[11];
    const float* b_conv   = (const float*)d_in[12];
    const float* Wo1      = (const float*)d_in[13];
    const float* bo1      = (const float*)d_in[14];
    const float* Wo2      = (const float*)d_in[15];
    const float* bo2      = (const float*)d_in[16];
    float* out = (float*)d_out;

    const int N = in_sizes[0];
    const int E = in_sizes[2];

    u16 *conth, *contl, *ch_, *cl_, *eh_, *el_, *hh_, *hl_, *th_, *tl_, *gh_, *gl_, *wh_, *wl_;
    int *p_deg, *p_off, *p_cur, *p_csr;
    cudaGetSymbolAddress((void**)&conth, g_cont_h);  cudaGetSymbolAddress((void**)&contl, g_cont_l);
    cudaGetSymbolAddress((void**)&ch_,   g_c_h);     cudaGetSymbolAddress((void**)&cl_,   g_c_l);
    cudaGetSymbolAddress((void**)&eh_,   g_e_h);     cudaGetSymbolAddress((void**)&el_,   g_e_l);
    cudaGetSymbolAddress((void**)&hh_,   g_h_h);     cudaGetSymbolAddress((void**)&hl_,   g_h_l);
    cudaGetSymbolAddress((void**)&th_,   g_t_h);     cudaGetSymbolAddress((void**)&tl_,   g_t_l);
    cudaGetSymbolAddress((void**)&gh_,   g_g_h);     cudaGetSymbolAddress((void**)&gl_,   g_g_l);
    cudaGetSymbolAddress((void**)&wh_,   g_w_h);     cudaGetSymbolAddress((void**)&wl_,   g_w_l);
    cudaGetSymbolAddress((void**)&p_deg, g_deg);     cudaGetSymbolAddress((void**)&p_off, g_off);
    cudaGetSymbolAddress((void**)&p_cur, g_cur);     cudaGetSymbolAddress((void**)&p_csr, g_csr);

    cudaFuncSetAttribute(pgemm, cudaFuncAttributeMaxDynamicSharedMemorySize, GSM);

    // ---- CSR build ----
    zero_int_kernel<<<(N + 255) / 256, 256>>>(p_deg, N);
    deg_kernel<<<(E + 255) / 256, 256>>>(dst, p_deg, E);
    scan_kernel<<<1, 1024>>>(p_deg, p_off, p_cur, N);
    fill_kernel<<<(E + 255) / 256, 256>>>(src, dst, p_cur, p_csr, E);

    // ---- split inputs to planes ----
    {
        int n1 = N * NCP;
        split_kernel<<<(n1 + 255) / 256, 256>>>(content, N, NC, NCP, conth, contl, nullptr);
        int n2 = N * ED;
        split_kernel<<<(n2 + 255) / 256, 256>>>(emb, N, ED, ED, eh_, el_, node_ids);
        split_kernel<<<(300 * NCP + 255) / 256, 256>>>(W_p1, 300, NC, NCP, wh_ + WP1, wl_ + WP1, nullptr);
        split_kernel<<<(256 * NCP + 255) / 256, 256>>>(W_p2, 256, NC, NCP, wh_ + WP2, wl_ + WP2, nullptr);
        split_kernel<<<(256 * 64 + 255) / 256, 256>>>(W_exp, 256, 64, 64, wh_ + WEXP, wl_ + WEXP, nullptr);
        split_kernel<<<(768 * 512 + 255) / 256, 256>>>(W_conv, 768, 512, 512, wh_ + WCONV, wl_ + WCONV, nullptr);
        split_kernel<<<(512 * 256 + 255) / 256, 256>>>(Wo1, 512, 256, 256, wh_ + WO1, wl_ + WO1, nullptr);
        split_kernel<<<(512 * 256 + 255) / 256, 256>>>(Wo2, 512, 256, 256, wh_ + WO2, wl_ + WO2, nullptr);
    }

    // ---- initial node representation ----
    // c = lrelu(content @ W_p1^T + b_p1)   [N,300] (Cs=320)
    pgemm<<<pg_grid(N, NC), 256, GSM>>>(conth, contl, conth, contl, NCP,
                                        wh_ + WP1, wl_ + WP1, b_p1,
                                        nullptr, nullptr,
                                        ch_, cl_, NCP, N, NC, NCP, 1);
    // t = lrelu(c @ W_p2^T + b_p2)         [N,256]
    pgemm<<<pg_grid(N, FD), 256, GSM>>>(ch_, cl_, ch_, cl_, NCP,
                                        wh_ + WP2, wl_ + WP2, b_p2,
                                        nullptr, nullptr,
                                        th_, tl_, FD, N, FD, NCP, 1);
    // h = lrelu(emb[ids] @ W_exp^T + b_exp) + t
    pgemm<<<pg_grid(N, FD), 256, GSM>>>(eh_, el_, eh_, el_, ED,
                                        wh_ + WEXP, wl_ + WEXP, b_exp,
                                        th_, tl_,
                                        hh_, hl_, FD, N, FD, ED, 1);

    const int warp_blocks = (N * 32 + 255) / 256;

    // ---- 3 SAGE layers ----
    for (int i = 0; i < 3; i++) {
        agg_pl<<<warp_blocks, 256>>>(hh_, hl_, p_off, p_csr, gh_, gl_, N);
        // t = (lrelu?)( [h, h_agg] @ W_conv[i]^T + b_conv[i] )
        pgemm<<<pg_grid(N, FD), 256, GSM>>>(hh_, hl_, gh_, gl_, FD,
                                            wh_ + WCONV + (size_t)i * FD * 2 * FD,
                                            wl_ + WCONV + (size_t)i * FD * 2 * FD,
                                            b_conv + (size_t)i * FD,
                                            nullptr, nullptr,
                                            th_, tl_, FD, N, FD, 2 * FD, (i < 2) ? 1 : 0);
        if (i < 2) {
            norm_pl<<<warp_blocks, 256>>>(th_, tl_, th_, tl_, nullptr, N);
            pgemm<<<pg_grid(N, FD), 256, GSM>>>(th_, tl_, th_, tl_, FD,
                                                wh_ + WO1 + (size_t)i * FD * FD,
                                                wl_ + WO1 + (size_t)i * FD * FD,
                                                bo1 + (size_t)i * FD,
                                                nullptr, nullptr,
                                                gh_, gl_, FD, N, FD, FD, 1);
            pgemm<<<pg_grid(N, FD), 256, GSM>>>(gh_, gl_, gh_, gl_, FD,
                                                wh_ + WO2 + (size_t)i * FD * FD,
                                                wl_ + WO2 + (size_t)i * FD * FD,
                                                bo2 + (size_t)i * FD,
                                                nullptr, nullptr,
                                                hh_, hl_, FD, N, FD, FD, 0);
        } else {
            norm_pl<<<warp_blocks, 256>>>(th_, tl_, nullptr, nullptr, out, N);
        }
    }
}